// round 9
// baseline (speedup 1.0000x reference)
#include <cuda_runtime.h>

// LengthRegulator, pointer-table form:
//   out[b, f, :] = xs[b, searchsorted(cumsum(ds[b]), f, right), :]
//   (0 if f >= total); all-zero ds rows treated as all-ones.
// B=32, T=512, D=384, MAX_FRAMES=2048.

#define BB 32
#define TT 512
#define DD 384
#define MF 2048
#define D4 (DD / 4)        // 96 float4 per frame
#define NFR (BB * MF)      // 65536 global frames
#define GTHR 192           // 2 x 96 lanes
#define FPBLK 8            // frames per gather block
#define GBLKS (NFR / FPBLK)// 8192 blocks

// Per-frame source row pointer (as integer). Padding frames point at zrow.
__device__ unsigned long long g_ptr[NFR];
// Zero row for padding frames (static zero-init, never written => deterministic).
__device__ float4 zrow[D4];

// ---------------------------------------------------------------------------
// Kernel A: per-batch inclusive scan + per-frame pointer table.
// One block per batch, 128 threads, 4 tokens each.
// ds dtype (int32 vs int64) detected at runtime: durations are in [0,4], so
// an int64 buffer has every odd int32 word == 0. P(false positive) = 0.2^128.
// ---------------------------------------------------------------------------
__global__ void __launch_bounds__(128)
lr_scan_kernel(const float4* __restrict__ xs, const int* __restrict__ ds32) {
    const int b    = blockIdx.x;
    const int tid  = threadIdx.x;
    const int lane = tid & 31;
    const int wid  = tid >> 5;                 // 4 warps

    __shared__ int s_warp[4];
    __shared__ int s_off[5];
    __shared__ int s_bad;

    const unsigned long long zptr = (unsigned long long)(size_t)zrow;

    if (tid == 0) s_bad = 0;
    const int samp = ds32[(tid * 256 + 1) & 16383];  // odd int32 words
    // init this batch's 2048 pointers to zrow (16 per thread, vectorized x2)
    {
        ulonglong2 zz; zz.x = zptr; zz.y = zptr;
#pragma unroll
        for (int k = 0; k < 8; k++)
            ((ulonglong2*)g_ptr)[b * (MF / 2) + tid + k * 128] = zz;
    }
    __syncthreads();
    if (samp != 0) atomicOr(&s_bad, 1);
    __syncthreads();
    const bool is64 = (s_bad == 0);

    // --- load 4 durations per thread (tokens 4*tid .. 4*tid+3) ---
    int d0, d1, d2, d3;
    if (is64) {
        longlong2 p = ((const longlong2*)ds32)[b * (TT / 2) + 2 * tid];
        longlong2 q = ((const longlong2*)ds32)[b * (TT / 2) + 2 * tid + 1];
        d0 = (int)p.x; d1 = (int)p.y; d2 = (int)q.x; d3 = (int)q.y;
    } else {
        int4 p = ((const int4*)ds32)[b * (TT / 4) + tid];
        d0 = p.x; d1 = p.y; d2 = p.z; d3 = p.w;
    }

    // --- hierarchical inclusive scan over 512 (4 per thread) ---
    const int sum4 = d0 + d1 + d2 + d3;
    int incl = sum4;
#pragma unroll
    for (int off = 1; off < 32; off <<= 1) {
        int n = __shfl_up_sync(0xFFFFFFFFu, incl, off);
        if (lane >= off) incl += n;
    }
    if (lane == 31) s_warp[wid] = incl;
    __syncthreads();
    if (wid == 0) {
        int w = (lane < 4) ? s_warp[lane] : 0;
#pragma unroll
        for (int off = 1; off < 4; off <<= 1) {
            int n = __shfl_up_sync(0xFFFFFFFFu, w, off);
            if (lane >= off) w += n;
        }
        if (lane < 4) s_off[lane + 1] = w;
        if (lane == 0) s_off[0] = 0;
    }
    __syncthreads();

    int excl = incl - sum4 + s_off[wid];       // exclusive prefix at token 4*tid
    const int total = s_off[4];

    const unsigned long long rowbase =
        (unsigned long long)(size_t)(xs + (size_t)b * TT * D4);

    if (total == 0) {
        // all-zero row => durations all 1 => identity map for f < T
#pragma unroll
        for (int k = 0; k < 4; k++) {
            const int t = 4 * tid + k;
            g_ptr[b * MF + t] = rowbase + (unsigned long long)t * (D4 * 16);
        }
    } else {
        int dd[4] = {d0, d1, d2, d3};
#pragma unroll
        for (int q = 0; q < 4; q++) {
            const unsigned long long rp =
                rowbase + (unsigned long long)(4 * tid + q) * (D4 * 16);
            const int en = excl + dd[q];
            for (int f = excl; f < en; f++)
                g_ptr[b * MF + f] = rp;
            excl = en;
        }
    }
}

// ---------------------------------------------------------------------------
// Kernel B: bandwidth mover. Block = 192 threads (2 x 96 lanes), 8 frames
// per block. Each thread has a FIXED column c = tid % 96; per frame it does
// one warp-uniform pointer load, one LDG.128, one streaming STG.128.
// ---------------------------------------------------------------------------
__global__ void __launch_bounds__(GTHR)
lr_gather_kernel(float4* __restrict__ out) {
    const int tid = threadIdx.x;
    const int c   = tid % D4;                  // fixed column (0..95)
    const int sub = tid / D4;                  // 0 or 1
    const int gf0 = blockIdx.x * FPBLK + sub;  // global frame, step 2

    unsigned long long p[4];
#pragma unroll
    for (int k = 0; k < 4; k++)
        p[k] = g_ptr[gf0 + 2 * k];             // warp-uniform broadcast load

    float4 v[4];
#pragma unroll
    for (int k = 0; k < 4; k++)
        v[k] = __ldg((const float4*)(size_t)p[k] + c);

#pragma unroll
    for (int k = 0; k < 4; k++)
        __stcs(&out[(size_t)(gf0 + 2 * k) * D4 + c], v[k]);
}

// ---------------------------------------------------------------------------
extern "C" void kernel_launch(void* const* d_in, const int* in_sizes, int n_in,
                              void* d_out, int out_size) {
    // Select pointers by element count (xs: 6,291,456 floats; ds: 16,384).
    const float* xs;
    const int* ds;
    if (in_sizes[0] > in_sizes[1]) {
        xs = (const float*)d_in[0];  ds = (const int*)d_in[1];
    } else {
        xs = (const float*)d_in[1];  ds = (const int*)d_in[0];
    }
    float4* out = (float4*)d_out;

    lr_scan_kernel<<<BB, 128>>>((const float4*)xs, ds);
    lr_gather_kernel<<<GBLKS, GTHR>>>(out);
}